// round 12
// baseline (speedup 1.0000x reference)
#include <cuda_runtime.h>
#include <cuda_fp16.h>
#include <cstdint>
#include <math.h>

#define NS 2048      // speakers
#define NG 8         // utts per speaker
#define ND 128       // embed dim
#define NR (NS*NG)   // 16384 rows
#define KC 128       // plain fp16, K = embed dim
#define NCH (KC/8)   // 16 16-byte chunks per row
#define ROWB (KC*2)  // 256 bytes per row
#define BM 128
#define BN 64
#define NTILES (NS/BN)   // 32
#define NT 512           // threads per CTA (16 warps = 4/SMSP)
#define NKS (KC/16)      // 8 k-steps

#define LOG2E 1.4426950408889634f
#define CEXP  (30.0f * LOG2E)
#define CLAMP2 (1e-6f * LOG2E)

// ---------------------------------------------------------------------------
// device globals (no allocation allowed)
// ---------------------------------------------------------------------------
__device__ float g_lbl[NR];                            // true label logit (fp32)
__device__ float g_dcorr[NR];                          // exp2 of fp16 diagonal logit
__device__ __align__(16) __half2 g_A2[NR * (KC/2)];    // [row][64] pairs (xn fp16)
__device__ __align__(16) __half2 g_B2[NS * (KC/2)];    // [spk][64] pairs (30*log2e*cent_n)

// ---------------------------------------------------------------------------
// PTX helpers (plain sm_80/90 — safe for compute_103)
// ---------------------------------------------------------------------------
__device__ __forceinline__ uint32_t smem_u32(const void* p) {
    uint32_t a;
    asm("{ .reg .u64 t; cvta.to.shared.u64 t, %1; cvt.u32.u64 %0, t; }" : "=r"(a) : "l"(p));
    return a;
}
#define CP16(dst32, gptr) \
    asm volatile("cp.async.cg.shared.global [%0], [%1], 16;" \
        :: "r"(dst32), "l"(__cvta_generic_to_global(gptr)) : "memory")
#define CP_COMMIT() asm volatile("cp.async.commit_group;" ::: "memory")
#define CP_WAIT0()  asm volatile("cp.async.wait_group 0;" ::: "memory")

__device__ __forceinline__ void ldsm4(unsigned r[4], uint32_t addr) {
    asm volatile("ldmatrix.sync.aligned.m8n8.x4.shared.b16 {%0,%1,%2,%3}, [%4];"
        : "=r"(r[0]), "=r"(r[1]), "=r"(r[2]), "=r"(r[3]) : "r"(addr));
}
__device__ __forceinline__ void mma16816(float d[4], const unsigned a[4],
                                         unsigned b0, unsigned b1) {
    asm volatile("mma.sync.aligned.m16n8k16.row.col.f32.f16.f16.f32 "
        "{%0,%1,%2,%3}, {%4,%5,%6,%7}, {%8,%9}, {%0,%1,%2,%3};"
        : "+f"(d[0]), "+f"(d[1]), "+f"(d[2]), "+f"(d[3])
        : "r"(a[0]), "r"(a[1]), "r"(a[2]), "r"(a[3]), "r"(b0), "r"(b1));
}

// ---------------------------------------------------------------------------
// Kernel 1: per-speaker prep
// ---------------------------------------------------------------------------
__device__ __forceinline__ void reduce8(const float v[NG], float (*scr)[4],
                                        float* out8, int lane, int warp, int tid) {
    #pragma unroll
    for (int g = 0; g < NG; g++) {
        float r = v[g];
        #pragma unroll
        for (int off = 16; off > 0; off >>= 1)
            r += __shfl_xor_sync(0xffffffffu, r, off);
        if (lane == 0) scr[g][warp] = r;
    }
    __syncthreads();
    if (tid < NG) out8[tid] = scr[tid][0] + scr[tid][1] + scr[tid][2] + scr[tid][3];
    __syncthreads();
}

__device__ __forceinline__ __half2 hi_pair(float a, float b) {
    return __halves2half2(__float2half_rn(a), __float2half_rn(b));
}
__device__ __forceinline__ float q16(float a) {
    return __half2float(__float2half_rn(a));
}

__global__ void prep_kernel(const float* __restrict__ x, float* __restrict__ out) {
    __shared__ float scr[NG][4];
    __shared__ float out8[NG];
    __shared__ float cnorm2;
    __shared__ float xs[NG][ND];
    __shared__ float cs[ND];

    const int s    = blockIdx.x;
    const int j    = threadIdx.x;       // 0..127
    const int lane = j & 31;
    const int warp = j >> 5;

    float xg[NG];
    #pragma unroll
    for (int g = 0; g < NG; g++) xg[g] = x[(s * NG + g) * ND + j];

    float v[NG];
    #pragma unroll
    for (int g = 0; g < NG; g++) v[g] = xg[g] * xg[g];
    reduce8(v, scr, out8, lane, warp, j);
    float xn[NG];
    float sum = 0.f;
    #pragma unroll
    for (int g = 0; g < NG; g++) {
        float nrm = fmaxf(sqrtf(out8[g]), 1e-12f);
        xn[g] = xg[g] / nrm;
        sum += xn[g];
    }

    float cent = sum * 0.125f;
    {
        float c2 = cent * cent;
        #pragma unroll
        for (int off = 16; off > 0; off >>= 1)
            c2 += __shfl_xor_sync(0xffffffffu, c2, off);
        if (lane == 0) scr[0][warp] = c2;
        __syncthreads();
        if (j == 0) cnorm2 = scr[0][0] + scr[0][1] + scr[0][2] + scr[0][3];
        __syncthreads();
    }
    // pre-scale centroid by 30*log2e: GEMM acc is then logit*log2e directly
    float centv = (30.f * LOG2E) * cent / fmaxf(sqrtf(cnorm2), 1e-8f);

    float exc[NG];
    #pragma unroll
    for (int g = 0; g < NG; g++) {
        exc[g] = (sum - xn[g]) * (1.0f / 7.0f);
        v[g] = exc[g] * exc[g];
    }
    reduce8(v, scr, out8, lane, warp, j);
    float e2[NG];
    #pragma unroll
    for (int g = 0; g < NG; g++) e2[g] = out8[g];
    #pragma unroll
    for (int g = 0; g < NG; g++)
        v[g] = xn[g] * exc[g] / fmaxf(sqrtf(e2[g]), 1e-8f);
    reduce8(v, scr, out8, lane, warp, j);
    if (j < NG) g_lbl[s * NG + j] = fmaxf(30.f * out8[j], 1e-6f);

    // diagonal correction: fp16-quantized dot (matches GEMM), exp2'ed
    {
        float cq = q16(centv);
        #pragma unroll
        for (int g = 0; g < NG; g++) v[g] = q16(xn[g]) * cq;
        reduce8(v, scr, out8, lane, warp, j);
        if (j < NG)
            g_dcorr[s * NG + j] = exp2f(fmaxf(out8[j], CLAMP2) - CEXP);
    }

    #pragma unroll
    for (int g = 0; g < NG; g++) xs[g][j] = xn[g];
    cs[j] = centv;
    __syncthreads();

    // A': plain fp16 pairs (64 per row)
    const int abase = s * NG * (KC/2);
    #pragma unroll
    for (int it = 0; it < (NG * (KC/2)) / 128; it++) {   // 4 iters
        int idx = it * 128 + j;
        int r = idx >> 6;
        int p = idx & 63;
        g_A2[abase + idx] = hi_pair(xs[r][2*p], xs[r][2*p+1]);
    }

    // B': fp16 pairs of pre-scaled centroid
    if (j < (KC/2)) g_B2[s * (KC/2) + j] = hi_pair(cs[2*j], cs[2*j+1]);

    if (s == 0 && j == 0) out[0] = 0.f;   // zero accumulator (d_out is poisoned)
}

// ---------------------------------------------------------------------------
// Kernel 2: HMMA GEMM (plain fp16, K=128) + fused online log-softmax.
// 128 CTAs x 512 threads (16 warps = 4/SMSP). Warp grid 4m x 4n,
// warp tile 32x16. A register-resident; B double-buffered.
// No diagonal logic in the hot loop (g_dcorr precomputed in prep).
// acc values are logit*log2e; e = exp2f(acc - 30*log2e).
// ---------------------------------------------------------------------------
#define SM_A     0
#define SM_B0    (BM * ROWB)               // 32768
#define SM_B1    (SM_B0 + BN * ROWB)       // 49152
#define SM_TOTAL (SM_B1 + BN * ROWB)       // 65536
#define BSTRIDE  (BN * ROWB)               // 16384 bytes of B per tile

__global__ void __launch_bounds__(NT, 1) gemm_kernel(float* __restrict__ out) {
    extern __shared__ char smem[];
    __shared__ float zbuf[BM][4];
    __shared__ float red[16];

    const uint32_t sb = smem_u32(smem);
    const int tid  = threadIdx.x;
    const int lane = tid & 31;
    const int wid  = tid >> 5;
    const int wm   = wid & 3;        // 0..3  (32-row slices)
    const int wn   = wid >> 2;       // 0..3  (16-col slices)
    const int br0  = blockIdx.x * BM;

    const char* gA = (const char*)g_A2;
    const char* gB = (const char*)g_B2;

    // ---- precomputed cp.async source/dest for B streaming (2 chunks/thread) ----
    const char* gptr[2];
    uint32_t    soff[2];
    #pragma unroll
    for (int ii = 0; ii < 2; ii++) {
        int idx = ii * NT + tid;
        int c = idx & (NCH - 1), n = idx >> 4;
        soff[ii] = n * ROWB + ((c ^ (n & 7)) << 4);
        gptr[ii] = gB + (size_t)n * ROWB + c * 16;
    }

    // ---- prologue: A tile + B tile 0 ----
    #pragma unroll
    for (int ii = 0; ii < (BM * NCH) / NT; ii++) {     // 4 iters
        int idx = ii * NT + tid;
        int c = idx & (NCH - 1), r = idx >> 4;
        CP16(sb + SM_A + r * ROWB + ((c ^ (r & 7)) << 4),
             gA + (size_t)(br0 + r) * ROWB + c * 16);
    }
    #pragma unroll
    for (int ii = 0; ii < 2; ii++)
        CP16(sb + SM_B0 + soff[ii], gptr[ii]);
    CP_COMMIT();

    // ---- B LDSM byte offsets, one per k-step (reused every tile) ----
    uint32_t bAddr[NKS];
    {
        int n = wn * 16 + ((lane >> 4) & 1) * 8 + (lane & 7);
        uint32_t bOff = n * ROWB;
        uint32_t bS = n & 7;
        uint32_t cbB = (lane >> 3) & 1;
        #pragma unroll
        for (int ks = 0; ks < NKS; ks++)
            bAddr[ks] = bOff + ((((2u*ks) | cbB) ^ bS) << 4);
    }

    // row slots: slot = mi*2 + h, row = wm*32 + mi*16 + h*8 + lane/4
    int rl[4];
    float zsum[4];
    #pragma unroll
    for (int sl = 0; sl < 4; sl++) {
        int mi = sl >> 1, h = sl & 1;
        rl[sl] = wm * 32 + mi * 16 + h * 8 + (lane >> 2);
        zsum[sl] = 0.f;
    }

    // ---- wait for A + B0, then load ALL A fragments into registers ----
    CP_WAIT0();
    __syncthreads();

    unsigned afr[2][NKS][4];    // 64 registers
    {
        const uint32_t cbA = (lane >> 4);
        #pragma unroll
        for (int mi = 0; mi < 2; mi++) {
            int row = wm * 32 + mi * 16 + (lane & 15);
            uint32_t base = sb + SM_A + row * ROWB;
            uint32_t s8 = row & 7;
            #pragma unroll
            for (int ks = 0; ks < NKS; ks++)
                ldsm4(afr[mi][ks], base + ((((2u*ks) | cbA) ^ s8) << 4));
        }
    }

    const uint32_t bufB[2] = { sb + SM_B0, sb + SM_B1 };

    for (int t = 0; t < NTILES; t++) {
        // prefetch B(t+1): B(t) ready and all warps past the barrier
        if (t + 1 < NTILES) {
            const uint32_t bb = bufB[(t + 1) & 1];
            const size_t gAdd = (size_t)(t + 1) * BSTRIDE;
            CP16(bb + soff[0], gptr[0] + gAdd);
            CP16(bb + soff[1], gptr[1] + gAdd);
            CP_COMMIT();
        }

        const uint32_t bcur = bufB[t & 1];
        float acc[2][2][4];
        #pragma unroll
        for (int mi = 0; mi < 2; mi++)
            #pragma unroll
            for (int nj = 0; nj < 2; nj++)
                #pragma unroll
                for (int q = 0; q < 4; q++) acc[mi][nj][q] = 0.f;

        #pragma unroll
        for (int ks = 0; ks < NKS; ks++) {          // 8 steps: 1 LDSM + 4 mma
            unsigned bf[4];
            ldsm4(bf, bcur + bAddr[ks]);
            #pragma unroll
            for (int mi = 0; mi < 2; mi++)
                #pragma unroll
                for (int nj = 0; nj < 2; nj++)
                    mma16816(acc[mi][nj], afr[mi][ks], bf[nj * 2], bf[nj * 2 + 1]);
        }

        // epilogue: unconditional clamp + exp2 + accumulate (no diag logic)
        #pragma unroll
        for (int mi = 0; mi < 2; mi++)
            #pragma unroll
            for (int nj = 0; nj < 2; nj++) {
                const float* a = acc[mi][nj];
                zsum[mi*2]   += exp2f(fmaxf(a[0], CLAMP2) - CEXP)
                              + exp2f(fmaxf(a[1], CLAMP2) - CEXP);
                zsum[mi*2+1] += exp2f(fmaxf(a[2], CLAMP2) - CEXP)
                              + exp2f(fmaxf(a[3], CLAMP2) - CEXP);
            }

        if (t + 1 < NTILES) {
            CP_WAIT0();
            __syncthreads();
        }
    }

    // reduce z across the 4 lanes of each quad (same row)
    #pragma unroll
    for (int sl = 0; sl < 4; sl++) {
        float z = zsum[sl];
        z += __shfl_xor_sync(0xffffffffu, z, 1);
        z += __shfl_xor_sync(0xffffffffu, z, 2);
        if ((lane & 3) == 0) zbuf[rl[sl]][wn] = z;
    }
    __syncthreads();

    // per-row loss + block reduce + single atomicAdd
    float loss = 0.f;
    if (tid < BM) {
        int row = br0 + tid;
        float lbl = g_lbl[row];
        float Z = (zbuf[tid][0] + zbuf[tid][1] + zbuf[tid][2] + zbuf[tid][3])
                - g_dcorr[row]
                + exp2f(lbl * LOG2E - CEXP);
        loss = 30.f + logf(Z) - lbl;
    }
    #pragma unroll
    for (int off = 16; off > 0; off >>= 1)
        loss += __shfl_xor_sync(0xffffffffu, loss, off);
    if (lane == 0) red[wid] = loss;
    __syncthreads();
    if (tid == 0) {
        float tot = 0.f;
        #pragma unroll
        for (int q = 0; q < 16; q++) tot += red[q];
        atomicAdd(out, tot * (1.f / (float)NR));
    }
}

// ---------------------------------------------------------------------------
extern "C" void kernel_launch(void* const* d_in, const int* in_sizes, int n_in,
                              void* d_out, int out_size) {
    const float* x = (const float*)d_in[0];
    float* out = (float*)d_out;

    prep_kernel<<<NS, 128>>>(x, out);

    cudaFuncSetAttribute(gemm_kernel, cudaFuncAttributeMaxDynamicSharedMemorySize, SM_TOTAL);
    gemm_kernel<<<NR / BM, NT, SM_TOTAL>>>(out);
}

// round 13
// speedup vs baseline: 1.0870x; 1.0870x over previous
#include <cuda_runtime.h>
#include <cuda_fp16.h>
#include <cstdint>
#include <math.h>

#define NS 2048      // speakers
#define NG 8         // utts per speaker
#define ND 128       // embed dim
#define NR (NS*NG)   // 16384 rows
#define KC 128       // plain fp16, K = embed dim
#define NCH (KC/8)   // 16 16-byte chunks per row
#define ROWB (KC*2)  // 256 bytes per row
#define BM 64
#define BN 64
#define NTILES (NS/BN)   // 32
#define NT 256           // threads per CTA (8 warps); 2 CTAs/SM
#define NKS (KC/16)      // 8 k-steps

#define LOG2E 1.4426950408889634f
#define CEXP  (30.0f * LOG2E)
#define CLAMP2 (1e-6f * LOG2E)

// ---------------------------------------------------------------------------
// device globals (no allocation allowed)
// ---------------------------------------------------------------------------
__device__ float g_lbl[NR];                            // true label logit (fp32)
__device__ float g_dcorr[NR];                          // exp2 of fp16 diagonal logit
__device__ __align__(16) __half2 g_A2[NR * (KC/2)];    // [row][64] pairs (xn fp16)
__device__ __align__(16) __half2 g_B2[NS * (KC/2)];    // [spk][64] pairs (30*log2e*cent_n)

// ---------------------------------------------------------------------------
// PTX helpers (plain sm_80/90 — safe for compute_103)
// ---------------------------------------------------------------------------
__device__ __forceinline__ uint32_t smem_u32(const void* p) {
    uint32_t a;
    asm("{ .reg .u64 t; cvta.to.shared.u64 t, %1; cvt.u32.u64 %0, t; }" : "=r"(a) : "l"(p));
    return a;
}
#define CP16(dst32, gptr) \
    asm volatile("cp.async.cg.shared.global [%0], [%1], 16;" \
        :: "r"(dst32), "l"(__cvta_generic_to_global(gptr)) : "memory")
#define CP_COMMIT() asm volatile("cp.async.commit_group;" ::: "memory")
#define CP_WAIT0()  asm volatile("cp.async.wait_group 0;" ::: "memory")

__device__ __forceinline__ void ldsm4(unsigned r[4], uint32_t addr) {
    asm volatile("ldmatrix.sync.aligned.m8n8.x4.shared.b16 {%0,%1,%2,%3}, [%4];"
        : "=r"(r[0]), "=r"(r[1]), "=r"(r[2]), "=r"(r[3]) : "r"(addr));
}
__device__ __forceinline__ void mma16816(float d[4], const unsigned a[4],
                                         unsigned b0, unsigned b1) {
    asm volatile("mma.sync.aligned.m16n8k16.row.col.f32.f16.f16.f32 "
        "{%0,%1,%2,%3}, {%4,%5,%6,%7}, {%8,%9}, {%0,%1,%2,%3};"
        : "+f"(d[0]), "+f"(d[1]), "+f"(d[2]), "+f"(d[3])
        : "r"(a[0]), "r"(a[1]), "r"(a[2]), "r"(a[3]), "r"(b0), "r"(b1));
}

__device__ __forceinline__ __half2 hi_pair(float a, float b) {
    return __halves2half2(__float2half_rn(a), __float2half_rn(b));
}
__device__ __forceinline__ float q16(float a) {
    return __half2float(__float2half_rn(a));
}
__device__ __forceinline__ float wred(float v) {
    #pragma unroll
    for (int off = 16; off > 0; off >>= 1)
        v += __shfl_xor_sync(0xffffffffu, v, off);
    return v;
}

// ---------------------------------------------------------------------------
// Kernel 1: warp-per-speaker prep, barrier-free.
// 256 blocks x 256 threads; warp w handles speaker blockIdx*8 + w.
// Lane l owns dims 4l..4l+3 (float4 loads, shfl-only reductions).
// ---------------------------------------------------------------------------
__global__ void __launch_bounds__(256) prep_kernel(const float* __restrict__ x,
                                                   float* __restrict__ out) {
    const int lane = threadIdx.x & 31;
    const int s = blockIdx.x * 8 + (threadIdx.x >> 5);

    // load 8 utterances x 4 dims
    float xv[NG][4];
    {
        const float4* xp = (const float4*)(x + (size_t)s * NG * ND);
        #pragma unroll
        for (int g = 0; g < NG; g++) {
            float4 v = xp[g * 32 + lane];
            xv[g][0] = v.x; xv[g][1] = v.y; xv[g][2] = v.z; xv[g][3] = v.w;
        }
    }

    // row norms -> xn; per-dim sum
    float xn[NG][4], sumd[4] = {0.f, 0.f, 0.f, 0.f};
    #pragma unroll
    for (int g = 0; g < NG; g++) {
        float n2 = wred(xv[g][0]*xv[g][0] + xv[g][1]*xv[g][1]
                      + xv[g][2]*xv[g][2] + xv[g][3]*xv[g][3]);
        float inv = 1.f / fmaxf(sqrtf(n2), 1e-12f);
        #pragma unroll
        for (int c = 0; c < 4; c++) {
            xn[g][c] = xv[g][c] * inv;
            sumd[c] += xn[g][c];
        }
    }

    // centroid -> normalized, pre-scaled by 30*log2e
    float cent[4], centv[4];
    {
        float c2 = 0.f;
        #pragma unroll
        for (int c = 0; c < 4; c++) { cent[c] = sumd[c] * 0.125f; c2 += cent[c]*cent[c]; }
        c2 = wred(c2);
        float sc = (30.f * LOG2E) / fmaxf(sqrtf(c2), 1e-8f);
        #pragma unroll
        for (int c = 0; c < 4; c++) centv[c] = cent[c] * sc;
    }

    // exclusive centroids: cosine + label logit; diag correction
    #pragma unroll
    for (int g = 0; g < NG; g++) {
        float e[4], e2 = 0.f;
        #pragma unroll
        for (int c = 0; c < 4; c++) {
            e[c] = (sumd[c] - xn[g][c]) * (1.0f / 7.0f);
            e2 += e[c] * e[c];
        }
        e2 = wred(e2);
        float inv = 1.f / fmaxf(sqrtf(e2), 1e-8f);
        float cg = 0.f;
        #pragma unroll
        for (int c = 0; c < 4; c++) cg += xn[g][c] * e[c];
        cg = wred(cg) * inv;

        float dq = 0.f;
        #pragma unroll
        for (int c = 0; c < 4; c++) dq += q16(xn[g][c]) * q16(centv[c]);
        dq = wred(dq);

        if (lane == g) {
            g_lbl[s * NG + g]   = fmaxf(30.f * cg, 1e-6f);
            g_dcorr[s * NG + g] = exp2f(fmaxf(dq, CLAMP2) - CEXP);
        }
    }

    // A': fp16 pairs — lane l writes pairs 2l, 2l+1 of each row
    #pragma unroll
    for (int g = 0; g < NG; g++) {
        __half2 h0 = hi_pair(xn[g][0], xn[g][1]);
        __half2 h1 = hi_pair(xn[g][2], xn[g][3]);
        *(uint2*)&g_A2[(size_t)(s * NG + g) * (KC/2) + 2 * lane] =
            make_uint2(*(unsigned*)&h0, *(unsigned*)&h1);
    }
    // B'
    {
        __half2 h0 = hi_pair(centv[0], centv[1]);
        __half2 h1 = hi_pair(centv[2], centv[3]);
        *(uint2*)&g_B2[(size_t)s * (KC/2) + 2 * lane] =
            make_uint2(*(unsigned*)&h0, *(unsigned*)&h1);
    }

    if (s == 0 && threadIdx.x == 0) out[0] = 0.f;   // zero accumulator
}

// ---------------------------------------------------------------------------
// Kernel 2: HMMA GEMM (plain fp16, K=128) + fused online log-softmax.
// 256 CTAs x 256 threads, 2 CTAs/SM (independent pipelines hide each other's
// barrier/epilogue bubbles). Warp grid 2m x 4n, warp tile 32x16.
// A register-resident; B double-buffered. acc = logit*log2e.
// ---------------------------------------------------------------------------
#define SM_A     0
#define SM_B0    (BM * ROWB)               // 16384
#define SM_B1    (SM_B0 + BN * ROWB)       // 32768
#define SM_TOTAL (SM_B1 + BN * ROWB)       // 49152
#define BSTRIDE  (BN * ROWB)               // 16384 bytes of B per tile

__global__ void __launch_bounds__(NT, 2) gemm_kernel(float* __restrict__ out) {
    extern __shared__ char smem[];
    __shared__ float zbuf[BM][4];
    __shared__ float red[8];

    const uint32_t sb = smem_u32(smem);
    const int tid  = threadIdx.x;
    const int lane = tid & 31;
    const int wid  = tid >> 5;
    const int wm   = wid & 1;        // 0..1  (32-row slices)
    const int wn   = wid >> 1;       // 0..3  (16-col slices)
    const int br0  = blockIdx.x * BM;

    const char* gA = (const char*)g_A2;
    const char* gB = (const char*)g_B2;

    // ---- precomputed cp.async source/dest for B streaming (4 chunks/thread) ----
    const char* gptr[4];
    uint32_t    soff[4];
    #pragma unroll
    for (int ii = 0; ii < 4; ii++) {
        int idx = ii * NT + tid;
        int c = idx & (NCH - 1), n = idx >> 4;
        soff[ii] = n * ROWB + ((c ^ (n & 7)) << 4);
        gptr[ii] = gB + (size_t)n * ROWB + c * 16;
    }

    // ---- prologue: A tile + B tile 0 ----
    #pragma unroll
    for (int ii = 0; ii < (BM * NCH) / NT; ii++) {     // 4 iters
        int idx = ii * NT + tid;
        int c = idx & (NCH - 1), r = idx >> 4;
        CP16(sb + SM_A + r * ROWB + ((c ^ (r & 7)) << 4),
             gA + (size_t)(br0 + r) * ROWB + c * 16);
    }
    #pragma unroll
    for (int ii = 0; ii < 4; ii++)
        CP16(sb + SM_B0 + soff[ii], gptr[ii]);
    CP_COMMIT();

    // ---- B LDSM byte offsets, one per k-step (reused every tile) ----
    uint32_t bAddr[NKS];
    {
        int n = wn * 16 + ((lane >> 4) & 1) * 8 + (lane & 7);
        uint32_t bOff = n * ROWB;
        uint32_t bS = n & 7;
        uint32_t cbB = (lane >> 3) & 1;
        #pragma unroll
        for (int ks = 0; ks < NKS; ks++)
            bAddr[ks] = bOff + ((((2u*ks) | cbB) ^ bS) << 4);
    }

    // row slots: slot = mi*2 + h, row = wm*32 + mi*16 + h*8 + lane/4
    int rl[4];
    float zsum[4];
    #pragma unroll
    for (int sl = 0; sl < 4; sl++) {
        int mi = sl >> 1, h = sl & 1;
        rl[sl] = wm * 32 + mi * 16 + h * 8 + (lane >> 2);
        zsum[sl] = 0.f;
    }

    // ---- wait for A + B0, then load ALL A fragments into registers ----
    CP_WAIT0();
    __syncthreads();

    unsigned afr[2][NKS][4];    // 64 registers
    {
        const uint32_t cbA = (lane >> 4);
        #pragma unroll
        for (int mi = 0; mi < 2; mi++) {
            int row = wm * 32 + mi * 16 + (lane & 15);
            uint32_t base = sb + SM_A + row * ROWB;
            uint32_t s8 = row & 7;
            #pragma unroll
            for (int ks = 0; ks < NKS; ks++)
                ldsm4(afr[mi][ks], base + ((((2u*ks) | cbA) ^ s8) << 4));
        }
    }

    const uint32_t bufB[2] = { sb + SM_B0, sb + SM_B1 };

    for (int t = 0; t < NTILES; t++) {
        // prefetch B(t+1): B(t) ready and all warps past the barrier
        if (t + 1 < NTILES) {
            const uint32_t bb = bufB[(t + 1) & 1];
            const size_t gAdd = (size_t)(t + 1) * BSTRIDE;
            CP16(bb + soff[0], gptr[0] + gAdd);
            CP16(bb + soff[1], gptr[1] + gAdd);
            CP16(bb + soff[2], gptr[2] + gAdd);
            CP16(bb + soff[3], gptr[3] + gAdd);
            CP_COMMIT();
        }

        const uint32_t bcur = bufB[t & 1];
        float acc[2][2][4];
        #pragma unroll
        for (int mi = 0; mi < 2; mi++)
            #pragma unroll
            for (int nj = 0; nj < 2; nj++)
                #pragma unroll
                for (int q = 0; q < 4; q++) acc[mi][nj][q] = 0.f;

        #pragma unroll
        for (int ks = 0; ks < NKS; ks++) {          // 8 steps: 1 LDSM + 4 mma
            unsigned bf[4];
            ldsm4(bf, bcur + bAddr[ks]);
            #pragma unroll
            for (int mi = 0; mi < 2; mi++)
                #pragma unroll
                for (int nj = 0; nj < 2; nj++)
                    mma16816(acc[mi][nj], afr[mi][ks], bf[nj * 2], bf[nj * 2 + 1]);
        }

        // epilogue: unconditional clamp + exp2 + accumulate (no diag logic)
        #pragma unroll
        for (int mi = 0; mi < 2; mi++)
            #pragma unroll
            for (int nj = 0; nj < 2; nj++) {
                const float* a = acc[mi][nj];
                zsum[mi*2]   += exp2f(fmaxf(a[0], CLAMP2) - CEXP)
                              + exp2f(fmaxf(a[1], CLAMP2) - CEXP);
                zsum[mi*2+1] += exp2f(fmaxf(a[2], CLAMP2) - CEXP)
                              + exp2f(fmaxf(a[3], CLAMP2) - CEXP);
            }

        if (t + 1 < NTILES) {
            CP_WAIT0();
            __syncthreads();
        }
    }

    // reduce z across the 4 lanes of each quad (same row)
    #pragma unroll
    for (int sl = 0; sl < 4; sl++) {
        float z = zsum[sl];
        z += __shfl_xor_sync(0xffffffffu, z, 1);
        z += __shfl_xor_sync(0xffffffffu, z, 2);
        if ((lane & 3) == 0) zbuf[rl[sl]][wn] = z;
    }
    __syncthreads();

    // per-row loss + block reduce + single atomicAdd
    float loss = 0.f;
    if (tid < BM) {
        int row = br0 + tid;
        float lbl = g_lbl[row];
        float Z = (zbuf[tid][0] + zbuf[tid][1] + zbuf[tid][2] + zbuf[tid][3])
                - g_dcorr[row]
                + exp2f(lbl * LOG2E - CEXP);
        loss = 30.f + logf(Z) - lbl;
    }
    #pragma unroll
    for (int off = 16; off > 0; off >>= 1)
        loss += __shfl_xor_sync(0xffffffffu, loss, off);
    if (lane == 0) red[wid] = loss;
    __syncthreads();
    if (tid == 0) {
        float tot = 0.f;
        #pragma unroll
        for (int q = 0; q < 8; q++) tot += red[q];
        atomicAdd(out, tot * (1.f / (float)NR));
    }
}

// ---------------------------------------------------------------------------
extern "C" void kernel_launch(void* const* d_in, const int* in_sizes, int n_in,
                              void* d_out, int out_size) {
    const float* x = (const float*)d_in[0];
    float* out = (float*)d_out;

    prep_kernel<<<NS / 8, 256>>>(x, out);

    cudaFuncSetAttribute(gemm_kernel, cudaFuncAttributeMaxDynamicSharedMemorySize, SM_TOTAL);
    gemm_kernel<<<NR / BM, NT, SM_TOTAL>>>(out);
}

// round 15
// speedup vs baseline: 1.0934x; 1.0059x over previous
#include <cuda_runtime.h>
#include <cuda_fp16.h>
#include <cstdint>
#include <math.h>

#define NS 2048      // speakers
#define NG 8         // utts per speaker
#define ND 128       // embed dim
#define NR (NS*NG)   // 16384 rows
#define KC 128       // plain fp16, K = embed dim
#define NCH (KC/8)   // 16 16-byte chunks per row
#define ROWB (KC*2)  // 256 bytes per row
#define BM 128
#define BN 64
#define NTILES (NS/BN)   // 32
#define NT 512           // threads per CTA (16 warps = 4/SMSP)
#define NKS (KC/16)      // 8 k-steps

#define LOG2E 1.4426950408889634f
#define CEXP  (30.0f * LOG2E)
#define CLAMP2 (1e-6f * LOG2E)

// ---------------------------------------------------------------------------
// device globals (no allocation allowed)
// ---------------------------------------------------------------------------
__device__ float g_lbl[NR];                            // true label logit (fp32)
__device__ float g_dcorr[NR];                          // exp2 of fp16 diag logit (RAW domain)
__device__ __align__(16) __half2 g_A2[NR * (KC/2)];    // [row][64] pairs (xn fp16)
__device__ __align__(16) __half2 g_B2[NS * (KC/2)];    // [spk][64] pairs (30*log2e*cent_n)

// ---------------------------------------------------------------------------
// PTX helpers (plain sm_80/90 — safe for compute_103)
// ---------------------------------------------------------------------------
__device__ __forceinline__ uint32_t smem_u32(const void* p) {
    uint32_t a;
    asm("{ .reg .u64 t; cvta.to.shared.u64 t, %1; cvt.u32.u64 %0, t; }" : "=r"(a) : "l"(p));
    return a;
}
#define CP16(dst32, gptr) \
    asm volatile("cp.async.cg.shared.global [%0], [%1], 16;" \
        :: "r"(dst32), "l"(__cvta_generic_to_global(gptr)) : "memory")
#define CP_COMMIT() asm volatile("cp.async.commit_group;" ::: "memory")
#define CP_WAIT0()  asm volatile("cp.async.wait_group 0;" ::: "memory")

__device__ __forceinline__ void ldsm4(unsigned r[4], uint32_t addr) {
    asm volatile("ldmatrix.sync.aligned.m8n8.x4.shared.b16 {%0,%1,%2,%3}, [%4];"
        : "=r"(r[0]), "=r"(r[1]), "=r"(r[2]), "=r"(r[3]) : "r"(addr));
}
__device__ __forceinline__ void mma16816(float d[4], const unsigned a[4],
                                         unsigned b0, unsigned b1) {
    asm volatile("mma.sync.aligned.m16n8k16.row.col.f32.f16.f16.f32 "
        "{%0,%1,%2,%3}, {%4,%5,%6,%7}, {%8,%9}, {%0,%1,%2,%3};"
        : "+f"(d[0]), "+f"(d[1]), "+f"(d[2]), "+f"(d[3])
        : "r"(a[0]), "r"(a[1]), "r"(a[2]), "r"(a[3]), "r"(b0), "r"(b1));
}

__device__ __forceinline__ __half2 hi_pair(float a, float b) {
    return __halves2half2(__float2half_rn(a), __float2half_rn(b));
}
__device__ __forceinline__ float q16(float a) {
    return __half2float(__float2half_rn(a));
}
__device__ __forceinline__ float wred(float v) {
    #pragma unroll
    for (int off = 16; off > 0; off >>= 1)
        v += __shfl_xor_sync(0xffffffffu, v, off);
    return v;
}

// ---------------------------------------------------------------------------
// Kernel 1: warp-per-speaker prep, barrier-free.
// ---------------------------------------------------------------------------
__global__ void __launch_bounds__(256) prep_kernel(const float* __restrict__ x,
                                                   float* __restrict__ out) {
    const int lane = threadIdx.x & 31;
    const int s = blockIdx.x * 8 + (threadIdx.x >> 5);

    float xv[NG][4];
    {
        const float4* xp = (const float4*)(x + (size_t)s * NG * ND);
        #pragma unroll
        for (int g = 0; g < NG; g++) {
            float4 v = xp[g * 32 + lane];
            xv[g][0] = v.x; xv[g][1] = v.y; xv[g][2] = v.z; xv[g][3] = v.w;
        }
    }

    float xn[NG][4], sumd[4] = {0.f, 0.f, 0.f, 0.f};
    #pragma unroll
    for (int g = 0; g < NG; g++) {
        float n2 = wred(xv[g][0]*xv[g][0] + xv[g][1]*xv[g][1]
                      + xv[g][2]*xv[g][2] + xv[g][3]*xv[g][3]);
        float inv = 1.f / fmaxf(sqrtf(n2), 1e-12f);
        #pragma unroll
        for (int c = 0; c < 4; c++) {
            xn[g][c] = xv[g][c] * inv;
            sumd[c] += xn[g][c];
        }
    }

    float cent[4], centv[4];
    {
        float c2 = 0.f;
        #pragma unroll
        for (int c = 0; c < 4; c++) { cent[c] = sumd[c] * 0.125f; c2 += cent[c]*cent[c]; }
        c2 = wred(c2);
        float sc = (30.f * LOG2E) / fmaxf(sqrtf(c2), 1e-8f);
        #pragma unroll
        for (int c = 0; c < 4; c++) centv[c] = cent[c] * sc;
    }

    #pragma unroll
    for (int g = 0; g < NG; g++) {
        float e[4], e2 = 0.f;
        #pragma unroll
        for (int c = 0; c < 4; c++) {
            e[c] = (sumd[c] - xn[g][c]) * (1.0f / 7.0f);
            e2 += e[c] * e[c];
        }
        e2 = wred(e2);
        float inv = 1.f / fmaxf(sqrtf(e2), 1e-8f);
        float cg = 0.f;
        #pragma unroll
        for (int c = 0; c < 4; c++) cg += xn[g][c] * e[c];
        cg = wred(cg) * inv;

        float dq = 0.f;
        #pragma unroll
        for (int c = 0; c < 4; c++) dq += q16(xn[g][c]) * q16(centv[c]);
        dq = wred(dq);

        if (lane == g) {
            g_lbl[s * NG + g]   = fmaxf(30.f * cg, 1e-6f);
            g_dcorr[s * NG + g] = exp2f(fmaxf(dq, CLAMP2));   // RAW domain
        }
    }

    #pragma unroll
    for (int g = 0; g < NG; g++) {
        __half2 h0 = hi_pair(xn[g][0], xn[g][1]);
        __half2 h1 = hi_pair(xn[g][2], xn[g][3]);
        *(uint2*)&g_A2[(size_t)(s * NG + g) * (KC/2) + 2 * lane] =
            make_uint2(*(unsigned*)&h0, *(unsigned*)&h1);
    }
    {
        __half2 h0 = hi_pair(centv[0], centv[1]);
        __half2 h1 = hi_pair(centv[2], centv[3]);
        *(uint2*)&g_B2[(size_t)s * (KC/2) + 2 * lane] =
            make_uint2(*(unsigned*)&h0, *(unsigned*)&h1);
    }

    if (s == 0 && threadIdx.x == 0) out[0] = 0.f;   // zero accumulator
}

// ---------------------------------------------------------------------------
// Kernel 2: HMMA GEMM (plain fp16, K=128) + fused online log-softmax.
// 128 CTAs x 512 threads (16 warps = 4/SMSP). Warp grid 8m x 2n,
// warp tile 16x32 (afr 32 regs). Two acc sets (ping-pong, 2-tile unroll);
// epilogue of tile t-1 interleaved INTO the mma k-loop of tile t so the
// tensor pipe is fed in every phase. Raw exp2 domain (CEXP folded to end).
// ---------------------------------------------------------------------------
#define SM_A     0
#define SM_B0    (BM * ROWB)               // 32768
#define SM_B1    (SM_B0 + BN * ROWB)       // 49152
#define SM_TOTAL (SM_B1 + BN * ROWB)       // 65536
#define BSTRIDE  (BN * ROWB)               // 16384 bytes of B per tile

struct TileCtx {
    uint32_t bufB[2];
    uint32_t swzOff[NKS];   // per-k-step swizzle offsets (same for both j2)
    uint32_t bOff[2];       // per-j2 row offsets
    const char* gptr[2];    // cp.async sources (this thread's 2 chunks)
    uint32_t    soff[2];    // cp.async smem dests
};

// One tile: prefetch B(t+1), run k-loop on B(t) into accCur, interleave
// epilogue of accPrev (tile t-1) between mma groups.
template <bool HAVE_PREV, bool HAVE_NEXT>
__device__ __forceinline__ void tile_body(
    const TileCtx& cx, int t,
    unsigned (&afr)[NKS][4],
    float (&accCur)[4][4], float (&accPrev)[4][4],
    float (&zsum)[2], int tid)
{
    if (HAVE_NEXT) {
        const uint32_t bb = cx.bufB[(t + 1) & 1];
        const size_t gAdd = (size_t)(t + 1) * BSTRIDE;
        CP16(bb + cx.soff[0], cx.gptr[0] + gAdd);
        CP16(bb + cx.soff[1], cx.gptr[1] + gAdd);
        CP_COMMIT();
    }

    const uint32_t bcur = cx.bufB[t & 1];
    #pragma unroll
    for (int nj = 0; nj < 4; nj++)
        #pragma unroll
        for (int q = 0; q < 4; q++) accCur[nj][q] = 0.f;

    #pragma unroll
    for (int ks = 0; ks < NKS; ks++) {      // 8 steps: 2 LDSM + 4 mma + 2-val epi
        unsigned bf0[4], bf1[4];
        ldsm4(bf0, bcur + cx.bOff[0] + cx.swzOff[ks]);
        ldsm4(bf1, bcur + cx.bOff[1] + cx.swzOff[ks]);
        mma16816(accCur[0], afr[ks], bf0[0], bf0[1]);
        mma16816(accCur[1], afr[ks], bf0[2], bf0[3]);
        mma16816(accCur[2], afr[ks], bf1[0], bf1[1]);
        mma16816(accCur[3], afr[ks], bf1[2], bf1[3]);

        if (HAVE_PREV) {
            // 2 values of accPrev per k-step: v = ks*2 + {0,1}
            #pragma unroll
            for (int u = 0; u < 2; u++) {
                const int v = ks * 2 + u;
                const int nj = v >> 2, q = v & 3;
                zsum[q >> 1] += exp2f(fmaxf(accPrev[nj][q], CLAMP2));
            }
        }
    }

    if (HAVE_NEXT) {
        CP_WAIT0();
        __syncthreads();
    }
}

__global__ void __launch_bounds__(NT, 1) gemm_kernel(float* __restrict__ out) {
    extern __shared__ char smem[];
    __shared__ float zbuf[BM][2];
    __shared__ float red[16];

    const uint32_t sb = smem_u32(smem);
    const int tid  = threadIdx.x;
    const int lane = tid & 31;
    const int wid  = tid >> 5;
    const int wm   = wid & 7;        // 0..7  (16-row slices)
    const int wn   = wid >> 3;       // 0..1  (32-col slices)
    const int br0  = blockIdx.x * BM;

    const char* gA = (const char*)g_A2;
    const char* gB = (const char*)g_B2;

    TileCtx cx;
    // cp.async chunks for B (2 per thread)
    #pragma unroll
    for (int ii = 0; ii < 2; ii++) {
        int idx = ii * NT + tid;
        int c = idx & (NCH - 1), n = idx >> 4;
        cx.soff[ii] = n * ROWB + ((c ^ (n & 7)) << 4);
        cx.gptr[ii] = gB + (size_t)n * ROWB + c * 16;
    }

    // ---- prologue: A tile + B tile 0 ----
    #pragma unroll
    for (int ii = 0; ii < (BM * NCH) / NT; ii++) {     // 4 iters
        int idx = ii * NT + tid;
        int c = idx & (NCH - 1), r = idx >> 4;
        CP16(sb + SM_A + r * ROWB + ((c ^ (r & 7)) << 4),
             gA + (size_t)(br0 + r) * ROWB + c * 16);
    }
    CP16(sb + SM_B0 + cx.soff[0], cx.gptr[0]);
    CP16(sb + SM_B0 + cx.soff[1], cx.gptr[1]);
    CP_COMMIT();

    // ---- B LDSM addressing: bS identical for j2=0/1 (16 = 0 mod 8) ----
    {
        int n0 = wn * 32 + ((lane >> 4) & 1) * 8 + (lane & 7);
        cx.bOff[0] = n0 * ROWB;
        cx.bOff[1] = (n0 + 16) * ROWB;
        uint32_t bS = n0 & 7;
        uint32_t cbB = (lane >> 3) & 1;
        #pragma unroll
        for (int ks = 0; ks < NKS; ks++)
            cx.swzOff[ks] = (((2u*ks) | cbB) ^ bS) << 4;
    }
    cx.bufB[0] = sb + SM_B0;
    cx.bufB[1] = sb + SM_B1;

    // row slots: m16 acc -> rows wm*16 + lane/4 and +8
    int rl0 = wm * 16 + (lane >> 2);
    float zsum[2] = {0.f, 0.f};

    // ---- wait for A + B0, load A fragments (32 regs) ----
    CP_WAIT0();
    __syncthreads();

    unsigned afr[NKS][4];
    {
        const uint32_t cbA = (lane >> 4);
        int row = wm * 16 + (lane & 15);
        uint32_t base = sb + SM_A + row * ROWB;
        uint32_t s8 = row & 7;
        #pragma unroll
        for (int ks = 0; ks < NKS; ks++)
            ldsm4(afr[ks], base + ((((2u*ks) | cbA) ^ s8) << 4));
    }

    float acc0[4][4], acc1[4][4];

    // tile 0 (no prev), tile 1 (prev = acc0)
    tile_body<false, true>(cx, 0, afr, acc0, acc1, zsum, tid);
    tile_body<true,  true>(cx, 1, afr, acc1, acc0, zsum, tid);
    #pragma unroll 1
    for (int t2 = 1; t2 < NTILES / 2 - 1; t2++) {
        tile_body<true, true>(cx, 2 * t2,     afr, acc0, acc1, zsum, tid);
        tile_body<true, true>(cx, 2 * t2 + 1, afr, acc1, acc0, zsum, tid);
    }
    tile_body<true, true >(cx, NTILES - 2, afr, acc0, acc1, zsum, tid);
    tile_body<true, false>(cx, NTILES - 1, afr, acc1, acc0, zsum, tid);

    // tail epilogue: tile NTILES-1 (in acc1)
    #pragma unroll
    for (int nj = 0; nj < 4; nj++)
        #pragma unroll
        for (int q = 0; q < 4; q++)
            zsum[q >> 1] += exp2f(fmaxf(acc1[nj][q], CLAMP2));

    // reduce across the 4 lanes of each quad (same row)
    #pragma unroll
    for (int sl = 0; sl < 2; sl++) {
        float z = zsum[sl];
        z += __shfl_xor_sync(0xffffffffu, z, 1);
        z += __shfl_xor_sync(0xffffffffu, z, 2);
        if ((lane & 3) == 0) zbuf[rl0 + sl * 8][wn] = z;
    }
    __syncthreads();

    // per-row loss + block reduce + single atomicAdd
    float loss = 0.f;
    if (tid < BM) {
        int row = br0 + tid;
        float lbl = g_lbl[row];
        float Zraw = zbuf[tid][0] + zbuf[tid][1]
                   - g_dcorr[row]
                   + exp2f(lbl * LOG2E);
        float Z = Zraw * exp2f(-CEXP);
        loss = 30.f + logf(Z) - lbl;
    }
    #pragma unroll
    for (int off = 16; off > 0; off >>= 1)
        loss += __shfl_xor_sync(0xffffffffu, loss, off);
    if (lane == 0) red[wid] = loss;
    __syncthreads();
    if (tid == 0) {
        float tot = 0.f;
        #pragma unroll
        for (int q = 0; q < 16; q++) tot += red[q];
        atomicAdd(out, tot * (1.f / (float)NR));
    }
}

// ---------------------------------------------------------------------------
extern "C" void kernel_launch(void* const* d_in, const int* in_sizes, int n_in,
                              void* d_out, int out_size) {
    const float* x = (const float*)d_in[0];
    float* out = (float*)d_out;

    prep_kernel<<<NS / 8, 256>>>(x, out);

    cudaFuncSetAttribute(gemm_kernel, cudaFuncAttributeMaxDynamicSharedMemorySize, SM_TOTAL);
    gemm_kernel<<<NR / BM, NT, SM_TOTAL>>>(out);
}

// round 16
// speedup vs baseline: 1.1403x; 1.0429x over previous
#include <cuda_runtime.h>
#include <cuda_fp16.h>
#include <cstdint>
#include <math.h>

#define NS 2048      // speakers
#define NG 8         // utts per speaker
#define ND 128       // embed dim
#define NR (NS*NG)   // 16384 rows
#define KC 128       // plain fp16, K = embed dim
#define NCH (KC/8)   // 16 16-byte chunks per row
#define ROWB (KC*2)  // 256 bytes per row
#define BM 128
#define BN 64
#define NTILES (NS/BN)   // 32
#define NPAIRS (NTILES/2) // 16
#define NT 512           // threads per CTA (16 warps = 4/SMSP)
#define NKS (KC/16)      // 8 k-steps

#define LOG2E 1.4426950408889634f
#define CEXP  (30.0f * LOG2E)
#define CLAMP2 (1e-6f * LOG2E)

// ---------------------------------------------------------------------------
// device globals (no allocation allowed)
// ---------------------------------------------------------------------------
__device__ float g_lbl[NR];                            // true label logit (fp32)
__device__ float g_dcorr[NR];                          // exp2 of fp16 diag logit (RAW domain)
__device__ __align__(16) __half2 g_A2[NR * (KC/2)];    // [row][64] pairs (xn fp16)
__device__ __align__(16) __half2 g_B2[NS * (KC/2)];    // [spk][64] pairs (30*log2e*cent_n)

// ---------------------------------------------------------------------------
// PTX helpers (plain sm_80/90 — safe for compute_103)
// ---------------------------------------------------------------------------
__device__ __forceinline__ uint32_t smem_u32(const void* p) {
    uint32_t a;
    asm("{ .reg .u64 t; cvta.to.shared.u64 t, %1; cvt.u32.u64 %0, t; }" : "=r"(a) : "l"(p));
    return a;
}
#define CP16(dst32, gptr) \
    asm volatile("cp.async.cg.shared.global [%0], [%1], 16;" \
        :: "r"(dst32), "l"(__cvta_generic_to_global(gptr)) : "memory")
#define CP_COMMIT() asm volatile("cp.async.commit_group;" ::: "memory")
#define CP_WAIT0()  asm volatile("cp.async.wait_group 0;" ::: "memory")

__device__ __forceinline__ void ldsm4(unsigned r[4], uint32_t addr) {
    asm volatile("ldmatrix.sync.aligned.m8n8.x4.shared.b16 {%0,%1,%2,%3}, [%4];"
        : "=r"(r[0]), "=r"(r[1]), "=r"(r[2]), "=r"(r[3]) : "r"(addr));
}
__device__ __forceinline__ void mma16816(float d[4], const unsigned a[4],
                                         unsigned b0, unsigned b1) {
    asm volatile("mma.sync.aligned.m16n8k16.row.col.f32.f16.f16.f32 "
        "{%0,%1,%2,%3}, {%4,%5,%6,%7}, {%8,%9}, {%0,%1,%2,%3};"
        : "+f"(d[0]), "+f"(d[1]), "+f"(d[2]), "+f"(d[3])
        : "r"(a[0]), "r"(a[1]), "r"(a[2]), "r"(a[3]), "r"(b0), "r"(b1));
}

__device__ __forceinline__ __half2 hi_pair(float a, float b) {
    return __halves2half2(__float2half_rn(a), __float2half_rn(b));
}
__device__ __forceinline__ float q16(float a) {
    return __half2float(__float2half_rn(a));
}
__device__ __forceinline__ float wred(float v) {
    #pragma unroll
    for (int off = 16; off > 0; off >>= 1)
        v += __shfl_xor_sync(0xffffffffu, v, off);
    return v;
}

// ---------------------------------------------------------------------------
// Kernel 1: warp-per-speaker prep, barrier-free.
// ---------------------------------------------------------------------------
__global__ void __launch_bounds__(256) prep_kernel(const float* __restrict__ x,
                                                   float* __restrict__ out) {
    const int lane = threadIdx.x & 31;
    const int s = blockIdx.x * 8 + (threadIdx.x >> 5);

    float xv[NG][4];
    {
        const float4* xp = (const float4*)(x + (size_t)s * NG * ND);
        #pragma unroll
        for (int g = 0; g < NG; g++) {
            float4 v = xp[g * 32 + lane];
            xv[g][0] = v.x; xv[g][1] = v.y; xv[g][2] = v.z; xv[g][3] = v.w;
        }
    }

    float xn[NG][4], sumd[4] = {0.f, 0.f, 0.f, 0.f};
    #pragma unroll
    for (int g = 0; g < NG; g++) {
        float n2 = wred(xv[g][0]*xv[g][0] + xv[g][1]*xv[g][1]
                      + xv[g][2]*xv[g][2] + xv[g][3]*xv[g][3]);
        float inv = 1.f / fmaxf(sqrtf(n2), 1e-12f);
        #pragma unroll
        for (int c = 0; c < 4; c++) {
            xn[g][c] = xv[g][c] * inv;
            sumd[c] += xn[g][c];
        }
    }

    float cent[4], centv[4];
    {
        float c2 = 0.f;
        #pragma unroll
        for (int c = 0; c < 4; c++) { cent[c] = sumd[c] * 0.125f; c2 += cent[c]*cent[c]; }
        c2 = wred(c2);
        float sc = (30.f * LOG2E) / fmaxf(sqrtf(c2), 1e-8f);
        #pragma unroll
        for (int c = 0; c < 4; c++) centv[c] = cent[c] * sc;
    }

    #pragma unroll
    for (int g = 0; g < NG; g++) {
        float e[4], e2 = 0.f;
        #pragma unroll
        for (int c = 0; c < 4; c++) {
            e[c] = (sumd[c] - xn[g][c]) * (1.0f / 7.0f);
            e2 += e[c] * e[c];
        }
        e2 = wred(e2);
        float inv = 1.f / fmaxf(sqrtf(e2), 1e-8f);
        float cg = 0.f;
        #pragma unroll
        for (int c = 0; c < 4; c++) cg += xn[g][c] * e[c];
        cg = wred(cg) * inv;

        float dq = 0.f;
        #pragma unroll
        for (int c = 0; c < 4; c++) dq += q16(xn[g][c]) * q16(centv[c]);
        dq = wred(dq);

        if (lane == g) {
            g_lbl[s * NG + g]   = fmaxf(30.f * cg, 1e-6f);
            g_dcorr[s * NG + g] = exp2f(fmaxf(dq, CLAMP2));   // RAW domain
        }
    }

    #pragma unroll
    for (int g = 0; g < NG; g++) {
        __half2 h0 = hi_pair(xn[g][0], xn[g][1]);
        __half2 h1 = hi_pair(xn[g][2], xn[g][3]);
        *(uint2*)&g_A2[(size_t)(s * NG + g) * (KC/2) + 2 * lane] =
            make_uint2(*(unsigned*)&h0, *(unsigned*)&h1);
    }
    {
        __half2 h0 = hi_pair(centv[0], centv[1]);
        __half2 h1 = hi_pair(centv[2], centv[3]);
        *(uint2*)&g_B2[(size_t)s * (KC/2) + 2 * lane] =
            make_uint2(*(unsigned*)&h0, *(unsigned*)&h1);
    }

    if (s == 0 && threadIdx.x == 0) out[0] = 0.f;   // zero accumulator
}

// ---------------------------------------------------------------------------
// Kernel 2: HMMA GEMM (plain fp16, K=128) + fused online log-softmax.
// 128 CTAs x 512 threads. Warp grid 8m x 2n, warp tile 16x32 (afr 32 regs).
// Tiles processed in PAIRS: one cp.async group + one wait + one barrier per
// 2 tiles (16 sync points instead of 32) -> warps de-phase within the pair
// and cover each other's LDSM/MUFU latency. Epilogue of tile t-1 interleaved
// into the mma k-loop of tile t (acc ping-pong). Raw exp2 domain.
// ---------------------------------------------------------------------------
#define SM_A     0
#define SM_B0    (BM * ROWB)               // 32768
#define PAIRB    (2 * BN * ROWB)           // 32768 bytes per pair
#define SM_TOTAL (SM_B0 + 2 * PAIRB)       // 98304

struct TileCtx {
    uint32_t bufPair[2];
    uint32_t swzOff[NKS];   // per-k-step swizzle offsets (same for both j2)
    uint32_t bOff[2];       // per-j2 row offsets
    const char* gptr[4];    // cp.async sources (this thread's 4 pair-chunks)
    uint32_t    soff[4];    // cp.async smem dests (pair-relative)
};

// Compute one 64-col tile from smem base bcur into accCur; interleave the
// exp2 epilogue of accPrev (previous tile) between mma groups.
template <bool HAVE_PREV>
__device__ __forceinline__ void compute_tile(
    const TileCtx& cx, uint32_t bcur,
    unsigned (&afr)[NKS][4],
    float (&accCur)[4][4], float (&accPrev)[4][4],
    float (&zsum)[2])
{
    #pragma unroll
    for (int nj = 0; nj < 4; nj++)
        #pragma unroll
        for (int q = 0; q < 4; q++) accCur[nj][q] = 0.f;

    #pragma unroll
    for (int ks = 0; ks < NKS; ks++) {      // 8 steps: 2 LDSM + 4 mma + 2-val epi
        unsigned bf0[4], bf1[4];
        ldsm4(bf0, bcur + cx.bOff[0] + cx.swzOff[ks]);
        ldsm4(bf1, bcur + cx.bOff[1] + cx.swzOff[ks]);
        mma16816(accCur[0], afr[ks], bf0[0], bf0[1]);
        mma16816(accCur[1], afr[ks], bf0[2], bf0[3]);
        mma16816(accCur[2], afr[ks], bf1[0], bf1[1]);
        mma16816(accCur[3], afr[ks], bf1[2], bf1[3]);

        if (HAVE_PREV) {
            #pragma unroll
            for (int u = 0; u < 2; u++) {
                const int v = ks * 2 + u;
                const int nj = v >> 2, q = v & 3;
                zsum[q >> 1] += exp2f(fmaxf(accPrev[nj][q], CLAMP2));
            }
        }
    }
}

__global__ void __launch_bounds__(NT, 1) gemm_kernel(float* __restrict__ out) {
    extern __shared__ char smem[];
    __shared__ float zbuf[BM][2];
    __shared__ float red[16];

    const uint32_t sb = smem_u32(smem);
    const int tid  = threadIdx.x;
    const int lane = tid & 31;
    const int wid  = tid >> 5;
    const int wm   = wid & 7;        // 0..7  (16-row slices)
    const int wn   = wid >> 3;       // 0..1  (32-col slices)
    const int br0  = blockIdx.x * BM;

    const char* gA = (const char*)g_A2;
    const char* gB = (const char*)g_B2;

    TileCtx cx;
    // cp.async chunks for a B PAIR (128 rows, 4 chunks per thread)
    #pragma unroll
    for (int ii = 0; ii < 4; ii++) {
        int idx = ii * NT + tid;
        int c = idx & (NCH - 1), n = idx >> 4;       // n in 0..127 (pair-relative)
        cx.soff[ii] = n * ROWB + ((c ^ (n & 7)) << 4);
        cx.gptr[ii] = gB + (size_t)n * ROWB + c * 16;
    }

    // ---- prologue: A tile + B pair 0 (tiles 0,1) ----
    #pragma unroll
    for (int ii = 0; ii < (BM * NCH) / NT; ii++) {     // 4 iters
        int idx = ii * NT + tid;
        int c = idx & (NCH - 1), r = idx >> 4;
        CP16(sb + SM_A + r * ROWB + ((c ^ (r & 7)) << 4),
             gA + (size_t)(br0 + r) * ROWB + c * 16);
    }
    #pragma unroll
    for (int ii = 0; ii < 4; ii++)
        CP16(sb + SM_B0 + cx.soff[ii], cx.gptr[ii]);
    CP_COMMIT();

    // ---- B LDSM addressing: bS identical for j2=0/1 (16 = 0 mod 8) ----
    {
        int n0 = wn * 32 + ((lane >> 4) & 1) * 8 + (lane & 7);
        cx.bOff[0] = n0 * ROWB;
        cx.bOff[1] = (n0 + 16) * ROWB;
        uint32_t bS = n0 & 7;
        uint32_t cbB = (lane >> 3) & 1;
        #pragma unroll
        for (int ks = 0; ks < NKS; ks++)
            cx.swzOff[ks] = (((2u*ks) | cbB) ^ bS) << 4;
    }
    cx.bufPair[0] = sb + SM_B0;
    cx.bufPair[1] = sb + SM_B0 + PAIRB;

    // row slots: m16 acc -> rows wm*16 + lane/4 and +8
    int rl0 = wm * 16 + (lane >> 2);
    float zsum[2] = {0.f, 0.f};

    // ---- wait for A + pair 0, load A fragments (32 regs) ----
    CP_WAIT0();
    __syncthreads();

    unsigned afr[NKS][4];
    {
        const uint32_t cbA = (lane >> 4);
        int row = wm * 16 + (lane & 15);
        uint32_t base = sb + SM_A + row * ROWB;
        uint32_t s8 = row & 7;
        #pragma unroll
        for (int ks = 0; ks < NKS; ks++)
            ldsm4(afr[ks], base + ((((2u*ks) | cbA) ^ s8) << 4));
    }

    float acc0[4][4], acc1[4][4];

    #pragma unroll 1
    for (int p = 0; p < NPAIRS; p++) {
        // prefetch pair p+1 into the buffer read at pair p-1 (barrier-protected)
        if (p + 1 < NPAIRS) {
            const uint32_t bb = cx.bufPair[(p + 1) & 1];
            const size_t gAdd = (size_t)(p + 1) * PAIRB;
            CP16(bb + cx.soff[0], cx.gptr[0] + gAdd);
            CP16(bb + cx.soff[1], cx.gptr[1] + gAdd);
            CP16(bb + cx.soff[2], cx.gptr[2] + gAdd);
            CP16(bb + cx.soff[3], cx.gptr[3] + gAdd);
            CP_COMMIT();
        }

        const uint32_t base = cx.bufPair[p & 1];
        if (p == 0) {
            compute_tile<false>(cx, base,             afr, acc0, acc1, zsum);
            compute_tile<true >(cx, base + PAIRB / 2, afr, acc1, acc0, zsum);
        } else {
            compute_tile<true >(cx, base,             afr, acc0, acc1, zsum);
            compute_tile<true >(cx, base + PAIRB / 2, afr, acc1, acc0, zsum);
        }

        if (p + 1 < NPAIRS) {
            CP_WAIT0();
            __syncthreads();
        }
    }

    // tail epilogue: last tile (in acc1)
    #pragma unroll
    for (int nj = 0; nj < 4; nj++)
        #pragma unroll
        for (int q = 0; q < 4; q++)
            zsum[q >> 1] += exp2f(fmaxf(acc1[nj][q], CLAMP2));

    // reduce across the 4 lanes of each quad (same row)
    #pragma unroll
    for (int sl = 0; sl < 2; sl++) {
        float z = zsum[sl];
        z += __shfl_xor_sync(0xffffffffu, z, 1);
        z += __shfl_xor_sync(0xffffffffu, z, 2);
        if ((lane & 3) == 0) zbuf[rl0 + sl * 8][wn] = z;
    }
    __syncthreads();

    // per-row loss + block reduce + single atomicAdd
    float loss = 0.f;
    if (tid < BM) {
        int row = br0 + tid;
        float lbl = g_lbl[row];
        float Zraw = zbuf[tid][0] + zbuf[tid][1]
                   - g_dcorr[row]
                   + exp2f(lbl * LOG2E);
        float Z = Zraw * exp2f(-CEXP);
        loss = 30.f + logf(Z) - lbl;
    }
    #pragma unroll
    for (int off = 16; off > 0; off >>= 1)
        loss += __shfl_xor_sync(0xffffffffu, loss, off);
    if (lane == 0) red[wid] = loss;
    __syncthreads();
    if (tid == 0) {
        float tot = 0.f;
        #pragma unroll
        for (int q = 0; q < 16; q++) tot += red[q];
        atomicAdd(out, tot * (1.f / (float)NR));
    }
}

// ---------------------------------------------------------------------------
extern "C" void kernel_launch(void* const* d_in, const int* in_sizes, int n_in,
                              void* d_out, int out_size) {
    const float* x = (const float*)d_in[0];
    float* out = (float*)d_out;

    prep_kernel<<<NS / 8, 256>>>(x, out);

    cudaFuncSetAttribute(gemm_kernel, cudaFuncAttributeMaxDynamicSharedMemorySize, SM_TOTAL);
    gemm_kernel<<<NR / BM, NT, SM_TOTAL>>>(out);
}